// round 1
// baseline (speedup 1.0000x reference)
#include <cuda_runtime.h>

#define B_   8
#define N_   16384
#define NC_  64
#define C_   256

// Scratch (device globals — no allocation allowed)
__device__ float g_G[C_ * C_];        // W_p @ W_c^T
__device__ float g_u[C_];             // W_p @ b_c
__device__ float g_v[C_];             // W_c @ b_p
__device__ float g_s0[1];             // b_p . b_c
__device__ float g_M[B_ * C_ * NC_];  // [b][c][k]
__device__ float g_t[B_ * NC_];       // [b][k]

__device__ __forceinline__ unsigned long long pack2(float x, float y) {
    unsigned long long r;
    asm("mov.b64 %0, {%1, %2};" : "=l"(r) : "f"(x), "f"(y));
    return r;
}
__device__ __forceinline__ void unpack2(unsigned long long v, float &x, float &y) {
    asm("mov.b64 {%0, %1}, %2;" : "=f"(x), "=f"(y) : "l"(v));
}
__device__ __forceinline__ void fma2(unsigned long long &acc, unsigned long long a, unsigned long long b) {
    asm("fma.rn.f32x2 %0, %1, %2, %3;" : "=l"(acc) : "l"(a), "l"(b), "l"(acc));
}

// ---------------------------------------------------------------------------
// Kernel 1: G = W_p W_c^T, u = W_p b_c, v = W_c b_p, s0 = b_p.b_c
// grid 256 (c), block 256 (e)
// ---------------------------------------------------------------------------
__global__ void prep_G_kernel(const float* __restrict__ Wp, const float* __restrict__ Wc,
                              const float* __restrict__ bp, const float* __restrict__ bc) {
    __shared__ __align__(16) float sWp[C_];
    int c = blockIdx.x;
    int e = threadIdx.x;
    sWp[e] = Wp[c * C_ + e];
    __syncthreads();

    const float4* wc4 = (const float4*)(Wc + e * C_);
    float acc = 0.f;
#pragma unroll 8
    for (int i = 0; i < C_ / 4; i++) {
        float4 w = wc4[i];
        acc += sWp[4*i]   * w.x;
        acc += sWp[4*i+1] * w.y;
        acc += sWp[4*i+2] * w.z;
        acc += sWp[4*i+3] * w.w;
    }
    g_G[c * C_ + e] = acc;

    if (e == 0) {
        float s = 0.f;
        for (int d = 0; d < C_; d++) s += sWp[d] * bc[d];
        g_u[c] = s;
    }
    if (c == 0) {
        const float4* bp4 = (const float4*)bp;
        float s = 0.f;
#pragma unroll 8
        for (int i = 0; i < C_ / 4; i++) {
            float4 w = wc4[i];
            float4 p = bp4[i];
            s += w.x*p.x + w.y*p.y + w.z*p.z + w.w*p.w;
        }
        g_v[e] = s;
        if (e == 0) {
            float t = 0.f;
            for (int d = 0; d < C_; d++) t += bp[d] * bc[d];
            g_s0[0] = t;
        }
    }
}

// ---------------------------------------------------------------------------
// Kernel 2: M[b,c,k] = sum_e G[c,e] Ctr[b,k,e] + u[c];  t[b,k] = v.Ctr[b,k] + s0
// grid 64 = (b * 8 + ktile), block 256 (c); 8 k per block
// ---------------------------------------------------------------------------
__global__ void prep_M_kernel(const float* __restrict__ cf) {
    __shared__ __align__(16) float sC[8 * C_];
    int b  = blockIdx.x >> 3;
    int kt = blockIdx.x & 7;
    int tid = threadIdx.x;

    const float4* src = (const float4*)(cf + (size_t)(b * NC_ + kt * 8) * C_);
    float4* s4 = (float4*)sC;
#pragma unroll
    for (int i = 0; i < 2; i++) s4[tid + 256 * i] = src[tid + 256 * i];
    __syncthreads();

    int c = tid;
    float u = g_u[c];
    float acc[8];
#pragma unroll
    for (int j = 0; j < 8; j++) acc[j] = u;

    const float4* g4 = (const float4*)(g_G + c * C_);
#pragma unroll 4
    for (int i = 0; i < C_ / 4; i++) {
        float4 g = g4[i];
#pragma unroll
        for (int j = 0; j < 8; j++) {
            acc[j] += g.x * sC[j * C_ + 4*i];
            acc[j] += g.y * sC[j * C_ + 4*i + 1];
            acc[j] += g.z * sC[j * C_ + 4*i + 2];
            acc[j] += g.w * sC[j * C_ + 4*i + 3];
        }
    }
#pragma unroll
    for (int j = 0; j < 8; j++)
        g_M[(size_t)(b * C_ + c) * NC_ + kt * 8 + j] = acc[j];

    if (c < 8) {
        float s = g_s0[0];
        for (int e = 0; e < C_; e++) s += g_v[e] * sC[c * C_ + e];
        g_t[b * NC_ + kt * 8 + c] = s;
    }
}

// ---------------------------------------------------------------------------
// Kernel 3 (main): per point n:
//   scores[k] = sum_c P[n,c] * M[b,c,k] + t[b,k]   (f32x2 packed over k-pairs)
//   softmax over k; out[n,c] = P[n,c] + sum_k w[k] * Ctr[b,k,c]
// grid 512 = (b * 64 + tile), block 256 (one thread per point)
// dynamic smem: 64 KB buffer, M tile in phase 1, Ctr tile in phase 2
// ---------------------------------------------------------------------------
extern __shared__ __align__(16) float sBuf[];

__global__ __launch_bounds__(256, 2)
void attn_main_kernel(const float* __restrict__ pf, const float* __restrict__ cf,
                      float* __restrict__ out) {
    __shared__ __align__(16) float st[NC_];

    int b    = blockIdx.x >> 6;
    int tile = blockIdx.x & 63;
    int tid  = threadIdx.x;

    // ---- load M[b] (256 x 64) into smem ----
    const float4* Ms = (const float4*)(g_M + (size_t)b * C_ * NC_);
    float4* s4 = (float4*)sBuf;
#pragma unroll
    for (int i = 0; i < 16; i++) s4[tid + 256 * i] = Ms[tid + 256 * i];
    if (tid < NC_) st[tid] = g_t[b * NC_ + tid];
    __syncthreads();

    size_t row = ((size_t)b * N_ + (size_t)tile * 256 + tid) * C_;
    const float4* p4 = (const float4*)(pf + row);

    // ---- phase 1: scores (64 accumulators as 32 f32x2 pairs), init with t ----
    unsigned long long acc[32];
    {
        const unsigned long long* t2 = (const unsigned long long*)st;
#pragma unroll
        for (int j = 0; j < 32; j++) acc[j] = t2[j];
    }
#pragma unroll 2
    for (int c0 = 0; c0 < C_ / 4; c0++) {
        float4 pv = p4[c0];
        float ps[4] = {pv.x, pv.y, pv.z, pv.w};
#pragma unroll
        for (int j = 0; j < 4; j++) {
            unsigned long long pp = pack2(ps[j], ps[j]);
            const ulonglong2* Mr = (const ulonglong2*)(sBuf + (4 * c0 + j) * NC_);
#pragma unroll
            for (int q = 0; q < 16; q++) {
                ulonglong2 mv = Mr[q];
                fma2(acc[2*q],     mv.x, pp);
                fma2(acc[2*q + 1], mv.y, pp);
            }
        }
    }

    // ---- softmax over 64 centroids (all-register, fully unrolled) ----
    float w[NC_];
#pragma unroll
    for (int j = 0; j < 32; j++) unpack2(acc[j], w[2*j], w[2*j + 1]);
    float mx = w[0];
#pragma unroll
    for (int k = 1; k < NC_; k++) mx = fmaxf(mx, w[k]);
    float sum = 0.f;
#pragma unroll
    for (int k = 0; k < NC_; k++) { w[k] = __expf(w[k] - mx); sum += w[k]; }
    float inv = 1.0f / sum;
#pragma unroll
    for (int k = 0; k < NC_; k++) w[k] *= inv;

    // ---- swap smem buffer to raw centroid features Ctr[b] (64 x 256) ----
    __syncthreads();
    const float4* Cs = (const float4*)(cf + (size_t)b * NC_ * C_);
#pragma unroll
    for (int i = 0; i < 16; i++) s4[tid + 256 * i] = Cs[tid + 256 * i];
    __syncthreads();

    // ---- phase 2: weighted = w @ Ctr, fused residual store ----
    float* orow = out + row;
#pragma unroll 1
    for (int ch = 0; ch < 8; ch++) {          // 8 chunks of 32 channels
        unsigned long long a2[16];
#pragma unroll
        for (int q = 0; q < 16; q++) a2[q] = 0ull;
#pragma unroll
        for (int k = 0; k < NC_; k++) {
            unsigned long long wk = pack2(w[k], w[k]);
            const ulonglong2* Cr = (const ulonglong2*)(sBuf + k * C_ + ch * 32);
#pragma unroll
            for (int q = 0; q < 8; q++) {
                ulonglong2 cv = Cr[q];
                fma2(a2[2*q],     cv.x, wk);
                fma2(a2[2*q + 1], cv.y, wk);
            }
        }
#pragma unroll
        for (int q = 0; q < 8; q++) {
            float4 pv = p4[ch * 8 + q];
            float x0, x1, x2, x3;
            unpack2(a2[2*q],     x0, x1);
            unpack2(a2[2*q + 1], x2, x3);
            float4 r;
            r.x = pv.x + x0; r.y = pv.y + x1; r.z = pv.z + x2; r.w = pv.w + x3;
            ((float4*)orow)[ch * 8 + q] = r;
        }
    }
}

// ---------------------------------------------------------------------------
extern "C" void kernel_launch(void* const* d_in, const int* in_sizes, int n_in,
                              void* d_out, int out_size) {
    const float* pf = (const float*)d_in[0];   // point_features   (B,N,C)
    const float* cf = (const float*)d_in[1];   // centroid_features(B,NC,C)
    const float* Wp = (const float*)d_in[2];   // (C,C)
    const float* bp = (const float*)d_in[3];   // (C,)
    const float* Wc = (const float*)d_in[4];   // (C,C)
    const float* bc = (const float*)d_in[5];   // (C,)
    float* out = (float*)d_out;

    static bool attr_set = false;  // idempotent attribute set (not device memory)
    if (!attr_set) {
        cudaFuncSetAttribute(attn_main_kernel,
                             cudaFuncAttributeMaxDynamicSharedMemorySize,
                             NC_ * C_ * sizeof(float));
        attr_set = true;
    }

    prep_G_kernel<<<C_, C_>>>(Wp, Wc, bp, bc);
    prep_M_kernel<<<B_ * 8, 256>>>(cf);
    attn_main_kernel<<<B_ * (N_ / 256), 256, NC_ * C_ * sizeof(float)>>>(pf, cf, out);
}

// round 2
// speedup vs baseline: 1.0093x; 1.0093x over previous
#include <cuda_runtime.h>

#define B_   8
#define N_   16384
#define NC_  64
#define C_   256

// Scratch (device globals — no allocation allowed)
__device__ float g_G[C_ * C_];        // W_p @ W_c^T
__device__ float g_u[C_];             // W_p @ b_c
__device__ float g_v[C_];             // W_c @ b_p
__device__ float g_s0[1];             // b_p . b_c
__device__ float g_M[B_ * C_ * NC_];  // [b][c][k]
__device__ float g_t[B_ * NC_];       // [b][k]

__device__ __forceinline__ unsigned long long pack2(float x, float y) {
    unsigned long long r;
    asm("mov.b64 %0, {%1, %2};" : "=l"(r) : "f"(x), "f"(y));
    return r;
}
__device__ __forceinline__ void unpack2(unsigned long long v, float &x, float &y) {
    asm("mov.b64 {%0, %1}, %2;" : "=f"(x), "=f"(y) : "l"(v));
}
__device__ __forceinline__ void fma2(unsigned long long &acc, unsigned long long a, unsigned long long b) {
    asm("fma.rn.f32x2 %0, %1, %2, %3;" : "=l"(acc) : "l"(a), "l"(b), "l"(acc));
}

// ---------------------------------------------------------------------------
// Kernel 1: G = W_p W_c^T, u = W_p b_c, v = W_c b_p, s0 = b_p.b_c
// grid 64, block 256: each block computes 4 rows of G; each thread streams its
// W_c row exactly once (16 MB total W_c traffic, L2-resident).
// ---------------------------------------------------------------------------
__global__ void prep_G_kernel(const float* __restrict__ Wp, const float* __restrict__ Wc,
                              const float* __restrict__ bp, const float* __restrict__ bc) {
    __shared__ __align__(16) float sWp[4 * C_];
    __shared__ __align__(16) float sbp[C_];
    int c0 = blockIdx.x * 4;
    int e  = threadIdx.x;

    // load 4 rows of Wp + bp into smem
    const float4* wp4 = (const float4*)(Wp + (size_t)c0 * C_);
    ((float4*)sWp)[e] = wp4[e];
    sbp[e] = bp[e];
    __syncthreads();

    const float4* wc4 = (const float4*)(Wc + (size_t)e * C_);
    float a0 = 0.f, a1 = 0.f, a2 = 0.f, a3 = 0.f;
#pragma unroll 8
    for (int i = 0; i < C_ / 4; i++) {
        float4 w = wc4[i];
#pragma unroll
        for (int j = 0; j < 4; j++) {
            const float* r = sWp + j * C_ + 4 * i;
            float s = r[0]*w.x + r[1]*w.y + r[2]*w.z + r[3]*w.w;
            if (j == 0) a0 += s; else if (j == 1) a1 += s;
            else if (j == 2) a2 += s; else a3 += s;
        }
    }
    g_G[(size_t)(c0 + 0) * C_ + e] = a0;
    g_G[(size_t)(c0 + 1) * C_ + e] = a1;
    g_G[(size_t)(c0 + 2) * C_ + e] = a2;
    g_G[(size_t)(c0 + 3) * C_ + e] = a3;

    // u for this block's 4 rows
    if (e < 4) {
        const float* r = sWp + e * C_;
        float s = 0.f;
        for (int d = 0; d < C_; d++) s += r[d] * bc[d];
        g_u[c0 + e] = s;
    }
    // v and s0 from block 0 only (second pass over W_c row: L1 hits)
    if (blockIdx.x == 0) {
        float s = 0.f;
#pragma unroll 8
        for (int i = 0; i < C_ / 4; i++) {
            float4 w = wc4[i];
            s += sbp[4*i]*w.x + sbp[4*i+1]*w.y + sbp[4*i+2]*w.z + sbp[4*i+3]*w.w;
        }
        g_v[e] = s;
        if (e == 0) {
            float t = 0.f;
            for (int d = 0; d < C_; d++) t += bp[d] * bc[d];
            g_s0[0] = t;
        }
    }
}

// ---------------------------------------------------------------------------
// Kernel 2: M[b,c,k] = sum_e G[c,e] Ctr[b,k,e] + u[c];  t[b,k] = v.Ctr[b,k] + s0
// grid 64 = (b * 8 + ktile), block 256 (c); 8 k per block
// ---------------------------------------------------------------------------
__global__ void prep_M_kernel(const float* __restrict__ cf) {
    __shared__ __align__(16) float sC[8 * C_];
    int b  = blockIdx.x >> 3;
    int kt = blockIdx.x & 7;
    int tid = threadIdx.x;

    const float4* src = (const float4*)(cf + (size_t)(b * NC_ + kt * 8) * C_);
    float4* s4 = (float4*)sC;
#pragma unroll
    for (int i = 0; i < 2; i++) s4[tid + 256 * i] = src[tid + 256 * i];
    __syncthreads();

    int c = tid;
    float u = g_u[c];
    float acc[8];
#pragma unroll
    for (int j = 0; j < 8; j++) acc[j] = u;

    const float4* g4 = (const float4*)(g_G + (size_t)c * C_);
#pragma unroll 4
    for (int i = 0; i < C_ / 4; i++) {
        float4 g = g4[i];
#pragma unroll
        for (int j = 0; j < 8; j++) {
            acc[j] += g.x * sC[j * C_ + 4*i];
            acc[j] += g.y * sC[j * C_ + 4*i + 1];
            acc[j] += g.z * sC[j * C_ + 4*i + 2];
            acc[j] += g.w * sC[j * C_ + 4*i + 3];
        }
    }
#pragma unroll
    for (int j = 0; j < 8; j++)
        g_M[(size_t)(b * C_ + c) * NC_ + kt * 8 + j] = acc[j];

    if (c < 8) {
        float s = g_s0[0];
        for (int e = 0; e < C_; e++) s += g_v[e] * sC[c * C_ + e];
        g_t[b * NC_ + kt * 8 + c] = s;
    }
}

// ---------------------------------------------------------------------------
// Kernel 3 (main): per point n:
//   scores[k] = sum_c P[n,c] * M[b,c,k] + t[b,k]   (f32x2 packed over k-pairs)
//   softmax IN PLACE on the packed pairs (weights never unpacked to an array);
//   out[n,c] = P[n,c] + inv * sum_k e[k] * Ctr[b,k,c]
// grid 512 = (b * 64 + tile), block 256 (one thread per point)
// dynamic smem: 64 KB buffer; M tile in phase 1, Ctr tile in phase 2
// ---------------------------------------------------------------------------
extern __shared__ __align__(16) float sBuf[];

__global__ __launch_bounds__(256, 2)
void attn_main_kernel(const float* __restrict__ pf, const float* __restrict__ cf,
                      float* __restrict__ out) {
    __shared__ __align__(16) float st[NC_];

    int b    = blockIdx.x >> 6;
    int tile = blockIdx.x & 63;
    int tid  = threadIdx.x;

    // ---- load M[b] (256 x 64) into smem ----
    const float4* Ms = (const float4*)(g_M + (size_t)b * C_ * NC_);
    float4* s4 = (float4*)sBuf;
#pragma unroll
    for (int i = 0; i < 16; i++) s4[tid + 256 * i] = Ms[tid + 256 * i];
    if (tid < NC_) st[tid] = g_t[b * NC_ + tid];
    __syncthreads();

    size_t row = ((size_t)b * N_ + (size_t)tile * 256 + tid) * C_;
    const float4* p4 = (const float4*)(pf + row);

    // ---- phase 1: scores (64 accumulators as 32 f32x2 pairs), init with t ----
    unsigned long long acc[32];
    {
        const unsigned long long* t2 = (const unsigned long long*)st;
#pragma unroll
        for (int j = 0; j < 32; j++) acc[j] = t2[j];
    }
#pragma unroll 2
    for (int c0 = 0; c0 < C_ / 4; c0++) {
        float4 pv = p4[c0];
        float ps[4] = {pv.x, pv.y, pv.z, pv.w};
#pragma unroll
        for (int j = 0; j < 4; j++) {
            unsigned long long pp = pack2(ps[j], ps[j]);
            const ulonglong2* Mr = (const ulonglong2*)(sBuf + (4 * c0 + j) * NC_);
#pragma unroll
            for (int q = 0; q < 16; q++) {
                ulonglong2 mv = Mr[q];
                fma2(acc[2*q],     mv.x, pp);
                fma2(acc[2*q + 1], mv.y, pp);
            }
        }
    }

    // ---- softmax over 64 centroids, IN PLACE on packed pairs ----
    float mx = -3.4e38f;
#pragma unroll
    for (int j = 0; j < 32; j++) {
        float x, y; unpack2(acc[j], x, y);
        mx = fmaxf(mx, fmaxf(x, y));
    }
    float sum = 0.f;
#pragma unroll
    for (int j = 0; j < 32; j++) {
        float x, y; unpack2(acc[j], x, y);
        x = __expf(x - mx); y = __expf(y - mx);
        sum += x + y;
        acc[j] = pack2(x, y);
    }
    float inv = 1.0f / sum;   // folded into the epilogue

    // ---- swap smem buffer to raw centroid features Ctr[b] (64 x 256) ----
    __syncthreads();
    const float4* Cs = (const float4*)(cf + (size_t)b * NC_ * C_);
#pragma unroll
    for (int i = 0; i < 16; i++) s4[tid + 256 * i] = Cs[tid + 256 * i];
    __syncthreads();

    // ---- phase 2: weighted = e @ Ctr, scaled by inv, fused residual store ----
    float* orow = out + row;
#pragma unroll 1
    for (int ch = 0; ch < 8; ch++) {          // 8 chunks of 32 channels
        unsigned long long a2[16];
#pragma unroll
        for (int q = 0; q < 16; q++) a2[q] = 0ull;
#pragma unroll
        for (int q = 0; q < 32; q++) {        // k-pairs
            float w0, w1; unpack2(acc[q], w0, w1);
            unsigned long long wk0 = pack2(w0, w0);
            unsigned long long wk1 = pack2(w1, w1);
            const ulonglong2* Cr0 = (const ulonglong2*)(sBuf + (2*q)     * C_ + ch * 32);
            const ulonglong2* Cr1 = (const ulonglong2*)(sBuf + (2*q + 1) * C_ + ch * 32);
#pragma unroll
            for (int r = 0; r < 8; r++) {
                ulonglong2 c0 = Cr0[r];
                fma2(a2[2*r],     c0.x, wk0);
                fma2(a2[2*r + 1], c0.y, wk0);
                ulonglong2 c1 = Cr1[r];
                fma2(a2[2*r],     c1.x, wk1);
                fma2(a2[2*r + 1], c1.y, wk1);
            }
        }
#pragma unroll
        for (int r = 0; r < 8; r++) {
            float4 pv = p4[ch * 8 + r];
            float x0, x1, x2, x3;
            unpack2(a2[2*r],     x0, x1);
            unpack2(a2[2*r + 1], x2, x3);
            float4 rr;
            rr.x = fmaf(inv, x0, pv.x);
            rr.y = fmaf(inv, x1, pv.y);
            rr.z = fmaf(inv, x2, pv.z);
            rr.w = fmaf(inv, x3, pv.w);
            ((float4*)orow)[ch * 8 + r] = rr;
        }
    }
}

// ---------------------------------------------------------------------------
extern "C" void kernel_launch(void* const* d_in, const int* in_sizes, int n_in,
                              void* d_out, int out_size) {
    const float* pf = (const float*)d_in[0];   // point_features   (B,N,C)
    const float* cf = (const float*)d_in[1];   // centroid_features(B,NC,C)
    const float* Wp = (const float*)d_in[2];   // (C,C)
    const float* bp = (const float*)d_in[3];   // (C,)
    const float* Wc = (const float*)d_in[4];   // (C,C)
    const float* bc = (const float*)d_in[5];   // (C,)
    float* out = (float*)d_out;

    static bool attr_set = false;  // idempotent attribute set (not device memory)
    if (!attr_set) {
        cudaFuncSetAttribute(attn_main_kernel,
                             cudaFuncAttributeMaxDynamicSharedMemorySize,
                             NC_ * C_ * sizeof(float));
        attr_set = true;
    }

    prep_G_kernel<<<64, C_>>>(Wp, Wc, bp, bc);
    prep_M_kernel<<<B_ * 8, 256>>>(cf);
    attn_main_kernel<<<B_ * (N_ / 256), 256, NC_ * C_ * sizeof(float)>>>(pf, cf, out);
}

// round 3
// speedup vs baseline: 1.0609x; 1.0511x over previous
#include <cuda_runtime.h>

#define B_   8
#define N_   16384
#define NC_  64
#define C_   256
#define STG_STRIDE 33   // 32 channels + 1 pad float -> conflict-free smem

// Scratch (device globals — no allocation allowed)
__device__ float g_G[C_ * C_];        // W_p @ W_c^T
__device__ float g_u[C_];             // W_p @ b_c
__device__ float g_v[C_];             // W_c @ b_p
__device__ float g_s0[1];             // b_p . b_c
__device__ float g_M[B_ * C_ * NC_];  // [b][c][k]
__device__ float g_t[B_ * NC_];       // [b][k]

__device__ __forceinline__ unsigned long long pack2(float x, float y) {
    unsigned long long r;
    asm("mov.b64 %0, {%1, %2};" : "=l"(r) : "f"(x), "f"(y));
    return r;
}
__device__ __forceinline__ void unpack2(unsigned long long v, float &x, float &y) {
    asm("mov.b64 {%0, %1}, %2;" : "=f"(x), "=f"(y) : "l"(v));
}
__device__ __forceinline__ void fma2(unsigned long long &acc, unsigned long long a, unsigned long long b) {
    asm("fma.rn.f32x2 %0, %1, %2, %3;" : "=l"(acc) : "l"(a), "l"(b), "l"(acc));
}
__device__ __forceinline__ float warp_sum(float s) {
#pragma unroll
    for (int off = 16; off; off >>= 1) s += __shfl_xor_sync(0xffffffffu, s, off);
    return s;
}

// ---------------------------------------------------------------------------
// Kernel 1: G = W_p W_c^T, u = W_p b_c, v = W_c b_p, s0 = b_p.b_c
// grid 64, block 256. Tails done by warp reductions (no serial scalar loops).
// ---------------------------------------------------------------------------
__global__ void prep_G_kernel(const float* __restrict__ Wp, const float* __restrict__ Wc,
                              const float* __restrict__ bp, const float* __restrict__ bc) {
    __shared__ __align__(16) float sWp[4 * C_];
    __shared__ __align__(16) float sbp[C_];
    int c0 = blockIdx.x * 4;
    int e  = threadIdx.x;
    int w  = e >> 5, l = e & 31;

    ((float4*)sWp)[e] = ((const float4*)(Wp + (size_t)c0 * C_))[e];
    sbp[e] = bp[e];
    __syncthreads();

    const float4* wc4 = (const float4*)(Wc + (size_t)e * C_);
    float a0 = 0.f, a1 = 0.f, a2 = 0.f, a3 = 0.f;
#pragma unroll 8
    for (int i = 0; i < C_ / 4; i++) {
        float4 v = wc4[i];
        const float* r0 = sWp + 4 * i;
        a0 += r0[0]*v.x + r0[1]*v.y + r0[2]*v.z + r0[3]*v.w;
        const float* r1 = sWp + C_ + 4 * i;
        a1 += r1[0]*v.x + r1[1]*v.y + r1[2]*v.z + r1[3]*v.w;
        const float* r2 = sWp + 2*C_ + 4 * i;
        a2 += r2[0]*v.x + r2[1]*v.y + r2[2]*v.z + r2[3]*v.w;
        const float* r3 = sWp + 3*C_ + 4 * i;
        a3 += r3[0]*v.x + r3[1]*v.y + r3[2]*v.z + r3[3]*v.w;
    }
    g_G[(size_t)(c0 + 0) * C_ + e] = a0;
    g_G[(size_t)(c0 + 1) * C_ + e] = a1;
    g_G[(size_t)(c0 + 2) * C_ + e] = a2;
    g_G[(size_t)(c0 + 3) * C_ + e] = a3;

    // u[c0+w] for w=0..3: warp reduction, coalesced bc loads
    if (w < 4) {
        float s = 0.f;
#pragma unroll
        for (int j = 0; j < 8; j++) s += sWp[w * C_ + l + 32 * j] * bc[l + 32 * j];
        s = warp_sum(s);
        if (l == 0) g_u[c0 + w] = s;
    }
    if (blockIdx.x == 0) {
        // v[e] = Wc row e . bp (vectorized; Wc row is L1-hot from the GEMM pass)
        float s = 0.f;
#pragma unroll 8
        for (int i = 0; i < C_ / 4; i++) {
            float4 v = wc4[i];
            s += sbp[4*i]*v.x + sbp[4*i+1]*v.y + sbp[4*i+2]*v.z + sbp[4*i+3]*v.w;
        }
        g_v[e] = s;
        // s0 = bp . bc via warp 4 reduction
        if (w == 4) {
            float s2 = 0.f;
#pragma unroll
            for (int j = 0; j < 8; j++) s2 += sbp[l + 32 * j] * bc[l + 32 * j];
            s2 = warp_sum(s2);
            if (l == 0) g_s0[0] = s2;
        }
    }
}

// ---------------------------------------------------------------------------
// Kernel 2: M[b,c,k] = sum_e G[c,e] Ctr[b,k,e] + u[c];  t[b,k] = v.Ctr[b,k] + s0
// grid 64 = (b * 8 + ktile), block 256 (c); 8 k per block. t via warp reduce.
// ---------------------------------------------------------------------------
__global__ void prep_M_kernel(const float* __restrict__ cf) {
    __shared__ __align__(16) float sC[8 * C_];
    int b  = blockIdx.x >> 3;
    int kt = blockIdx.x & 7;
    int tid = threadIdx.x;
    int w = tid >> 5, l = tid & 31;

    const float4* src = (const float4*)(cf + (size_t)(b * NC_ + kt * 8) * C_);
    float4* s4 = (float4*)sC;
#pragma unroll
    for (int i = 0; i < 2; i++) s4[tid + 256 * i] = src[tid + 256 * i];
    __syncthreads();

    int c = tid;
    float u = g_u[c];
    float acc[8];
#pragma unroll
    for (int j = 0; j < 8; j++) acc[j] = u;

    const float4* g4 = (const float4*)(g_G + (size_t)c * C_);
#pragma unroll 4
    for (int i = 0; i < C_ / 4; i++) {
        float4 g = g4[i];
#pragma unroll
        for (int j = 0; j < 8; j++) {
            acc[j] += g.x * sC[j * C_ + 4*i];
            acc[j] += g.y * sC[j * C_ + 4*i + 1];
            acc[j] += g.z * sC[j * C_ + 4*i + 2];
            acc[j] += g.w * sC[j * C_ + 4*i + 3];
        }
    }
#pragma unroll
    for (int j = 0; j < 8; j++)
        g_M[(size_t)(b * C_ + c) * NC_ + kt * 8 + j] = acc[j];

    // t[b, kt*8 + w]: warp w reduces v . Ctr row w (coalesced g_v loads)
    {
        float s = 0.f;
#pragma unroll
        for (int j = 0; j < 8; j++) s += g_v[l + 32 * j] * sC[w * C_ + l + 32 * j];
        s = warp_sum(s);
        if (l == 0) g_t[b * NC_ + kt * 8 + w] = s + g_s0[0];
    }
}

// ---------------------------------------------------------------------------
// Kernel 3 (main). Thread-per-point, but ALL global traffic is coalesced via a
// padded smem stage (32-channel chunks). M / Ctr reads are broadcast LDS.
//   phase 1: scores[k] = sum_c P[n,c]*M[b,c,k] + t[b,k]  (packed f32x2 pairs)
//   softmax in place on packed pairs
//   phase 2: out[n,c] = P[n,c] + inv * sum_k e[k]*Ctr[b,k,c], stored via stage
// grid 512 = (b*64 + tile), block 256.
// dyn smem: sBuf 64KB (M then Ctr) + stage 256*33 floats = 97.0 KB
// ---------------------------------------------------------------------------
__global__ __launch_bounds__(256, 2)
void attn_main_kernel(const float* __restrict__ pf, const float* __restrict__ cf,
                      float* __restrict__ out) {
    extern __shared__ __align__(16) float sm[];
    float* sBuf   = sm;            // 16384 floats
    float* sStage = sm + 16384;    // 256 * 33 floats
    __shared__ __align__(16) float st[NC_];

    int b    = blockIdx.x >> 6;
    int tile = blockIdx.x & 63;
    int tid  = threadIdx.x;

    // ---- load M[b] (256 x 64) into sBuf (coalesced) ----
    const float4* Ms = (const float4*)(g_M + (size_t)b * C_ * NC_);
    float4* s4 = (float4*)sBuf;
#pragma unroll
    for (int i = 0; i < 16; i++) s4[tid + 256 * i] = Ms[tid + 256 * i];
    if (tid < NC_) st[tid] = g_t[b * NC_ + tid];
    __syncthreads();

    size_t ptbase = ((size_t)b * N_ + (size_t)tile * 256);  // first point of block
    const float* pbase = pf + ptbase * C_;
    float* obase = out + ptbase * C_;
    float* myrow = sStage + tid * STG_STRIDE;

    // ---- phase 1: scores (64 accs as 32 f32x2 pairs), init with t ----
    unsigned long long acc[32];
    {
        const unsigned long long* t2 = (const unsigned long long*)st;
#pragma unroll
        for (int j = 0; j < 32; j++) acc[j] = t2[j];
    }

#pragma unroll 1
    for (int ch = 0; ch < 8; ch++) {
        // cooperative coalesced load of P[256 pts][32 ch] into stage
#pragma unroll
        for (int i = 0; i < 8; i++) {
            int q  = tid + 256 * i;
            int pt = q >> 3, pos = q & 7;
            float4 v = *(const float4*)(pbase + (size_t)pt * C_ + ch * 32 + pos * 4);
            float* d = sStage + pt * STG_STRIDE + pos * 4;
            d[0] = v.x; d[1] = v.y; d[2] = v.z; d[3] = v.w;
        }
        __syncthreads();
#pragma unroll
        for (int j = 0; j < 32; j++) {
            float p = myrow[j];
            unsigned long long pp = pack2(p, p);
            const ulonglong2* Mr = (const ulonglong2*)(sBuf + (ch * 32 + j) * NC_);
#pragma unroll
            for (int q = 0; q < 16; q++) {
                ulonglong2 mv = Mr[q];
                fma2(acc[2*q],     mv.x, pp);
                fma2(acc[2*q + 1], mv.y, pp);
            }
        }
        __syncthreads();
    }

    // ---- softmax over 64 centroids, in place on packed pairs ----
    float mx = -3.4e38f;
#pragma unroll
    for (int j = 0; j < 32; j++) {
        float x, y; unpack2(acc[j], x, y);
        mx = fmaxf(mx, fmaxf(x, y));
    }
    float sum = 0.f;
#pragma unroll
    for (int j = 0; j < 32; j++) {
        float x, y; unpack2(acc[j], x, y);
        x = __expf(x - mx); y = __expf(y - mx);
        sum += x + y;
        acc[j] = pack2(x, y);
    }
    float inv = 1.0f / sum;

    // ---- swap sBuf to raw centroid features Ctr[b] (64 x 256), coalesced ----
    const float4* Cs = (const float4*)(cf + (size_t)b * NC_ * C_);
#pragma unroll
    for (int i = 0; i < 16; i++) s4[tid + 256 * i] = Cs[tid + 256 * i];
    __syncthreads();

    // ---- phase 2: per 32-channel chunk: weighted sum + residual, staged out ----
#pragma unroll 1
    for (int ch = 0; ch < 8; ch++) {
        // stage P chunk (residual input), coalesced
#pragma unroll
        for (int i = 0; i < 8; i++) {
            int q  = tid + 256 * i;
            int pt = q >> 3, pos = q & 7;
            float4 v = *(const float4*)(pbase + (size_t)pt * C_ + ch * 32 + pos * 4);
            float* d = sStage + pt * STG_STRIDE + pos * 4;
            d[0] = v.x; d[1] = v.y; d[2] = v.z; d[3] = v.w;
        }

        // accumulate 32 output channels (16 f32x2 pairs); independent of stage
        unsigned long long a2[16];
#pragma unroll
        for (int q = 0; q < 16; q++) a2[q] = 0ull;
#pragma unroll
        for (int q = 0; q < 32; q++) {        // k-pairs
            float w0, w1; unpack2(acc[q], w0, w1);
            unsigned long long wk0 = pack2(w0, w0);
            unsigned long long wk1 = pack2(w1, w1);
            const ulonglong2* Cr0 = (const ulonglong2*)(sBuf + (2*q)     * C_ + ch * 32);
            const ulonglong2* Cr1 = (const ulonglong2*)(sBuf + (2*q + 1) * C_ + ch * 32);
#pragma unroll
            for (int r = 0; r < 8; r++) {
                ulonglong2 c0 = Cr0[r];
                fma2(a2[2*r],     c0.x, wk0);
                fma2(a2[2*r + 1], c0.y, wk0);
                ulonglong2 c1 = Cr1[r];
                fma2(a2[2*r],     c1.x, wk1);
                fma2(a2[2*r + 1], c1.y, wk1);
            }
        }
        __syncthreads();   // stage filled by all threads

        // residual add in own stage row (no cross-thread hazard)
#pragma unroll
        for (int r = 0; r < 16; r++) {
            float x0, x1; unpack2(a2[r], x0, x1);
            myrow[2*r]     = fmaf(inv, x0, myrow[2*r]);
            myrow[2*r + 1] = fmaf(inv, x1, myrow[2*r + 1]);
        }
        __syncthreads();   // rows finalized

        // cooperative coalesced store
#pragma unroll
        for (int i = 0; i < 8; i++) {
            int q  = tid + 256 * i;
            int pt = q >> 3, pos = q & 7;
            const float* s = sStage + pt * STG_STRIDE + pos * 4;
            float4 v; v.x = s[0]; v.y = s[1]; v.z = s[2]; v.w = s[3];
            *(float4*)(obase + (size_t)pt * C_ + ch * 32 + pos * 4) = v;
        }
        __syncthreads();   // protect stage before next chunk's fill
    }
}

// ---------------------------------------------------------------------------
extern "C" void kernel_launch(void* const* d_in, const int* in_sizes, int n_in,
                              void* d_out, int out_size) {
    const float* pf = (const float*)d_in[0];   // point_features   (B,N,C)
    const float* cf = (const float*)d_in[1];   // centroid_features(B,NC,C)
    const float* Wp = (const float*)d_in[2];   // (C,C)
    const float* bp = (const float*)d_in[3];   // (C,)
    const float* Wc = (const float*)d_in[4];   // (C,C)
    const float* bc = (const float*)d_in[5];   // (C,)
    float* out = (float*)d_out;

    const int smem_bytes = (16384 + 256 * STG_STRIDE) * sizeof(float);

    static bool attr_set = false;  // idempotent attribute set (not device memory)
    if (!attr_set) {
        cudaFuncSetAttribute(attn_main_kernel,
                             cudaFuncAttributeMaxDynamicSharedMemorySize,
                             smem_bytes);
        attr_set = true;
    }

    prep_G_kernel<<<64, C_>>>(Wp, Wc, bp, bc);
    prep_M_kernel<<<B_ * 8, 256>>>(cf);
    attn_main_kernel<<<B_ * (N_ / 256), 256, smem_bytes>>>(pf, cf, out);
}

// round 4
// speedup vs baseline: 1.7120x; 1.6137x over previous
#include <cuda_runtime.h>

#define B_   8
#define N_   16384
#define NC_  64
#define C_   256
#define TP_  128           // points per block (main kernel)
#define SP_STRIDE 72       // sP row stride (floats)
#define SE_STRIDE 76       // sE row stride (floats)

// Scratch (device globals — no allocation allowed)
__device__ float g_G[C_ * C_];        // W_p @ W_c^T
__device__ float g_u[C_];             // W_p @ b_c
__device__ float g_v[C_];             // W_c @ b_p
__device__ float g_s0[1];             // b_p . b_c
__device__ float g_M[B_ * C_ * NC_];  // [b][c][k]
__device__ float g_t[B_ * NC_];       // [b][k]

typedef unsigned long long ull;

__device__ __forceinline__ ull pack2(float x, float y) {
    ull r; asm("mov.b64 %0, {%1, %2};" : "=l"(r) : "f"(x), "f"(y)); return r;
}
__device__ __forceinline__ void unpack2(ull v, float &x, float &y) {
    asm("mov.b64 {%0, %1}, %2;" : "=f"(x), "=f"(y) : "l"(v));
}
__device__ __forceinline__ void fma2(ull &acc, ull a, ull b) {
    asm("fma.rn.f32x2 %0, %1, %2, %3;" : "=l"(acc) : "l"(a), "l"(b), "l"(acc));
}
__device__ __forceinline__ float warp_sum(float s) {
#pragma unroll
    for (int off = 16; off; off >>= 1) s += __shfl_xor_sync(0xffffffffu, s, off);
    return s;
}

// ---------------------------------------------------------------------------
// Kernel 1: G = W_p W_c^T (+ u, v, s0). grid 256 (1 G-row per block), block 256.
// ---------------------------------------------------------------------------
__global__ void prep_G_kernel(const float* __restrict__ Wp, const float* __restrict__ Wc,
                              const float* __restrict__ bp, const float* __restrict__ bc) {
    __shared__ __align__(16) float sWp[C_];
    int c = blockIdx.x;
    int e = threadIdx.x;
    int w = e >> 5, l = e & 31;

    sWp[e] = Wp[(size_t)c * C_ + e];
    __syncthreads();

    const float4* wc4 = (const float4*)(Wc + (size_t)e * C_);
    float a = 0.f;
#pragma unroll 8
    for (int i = 0; i < C_ / 4; i++) {
        float4 v = wc4[i];
        a += sWp[4*i]*v.x + sWp[4*i+1]*v.y + sWp[4*i+2]*v.z + sWp[4*i+3]*v.w;
    }
    g_G[(size_t)c * C_ + e] = a;

    if (w == 0) {   // u[c] = Wp_row_c . bc
        float s = 0.f;
#pragma unroll
        for (int j = 0; j < 8; j++) s += sWp[l + 32*j] * bc[l + 32*j];
        s = warp_sum(s);
        if (l == 0) g_u[c] = s;
    }
    if (blockIdx.x == 0) {
        float s = 0.f;
#pragma unroll 8
        for (int i = 0; i < C_ / 4; i++) {
            float4 v = wc4[i];
            s += bp[4*i]*v.x + bp[4*i+1]*v.y + bp[4*i+2]*v.z + bp[4*i+3]*v.w;
        }
        g_v[e] = s;
        if (w == 1) {
            float s2 = 0.f;
#pragma unroll
            for (int j = 0; j < 8; j++) s2 += bp[l + 32*j] * bc[l + 32*j];
            s2 = warp_sum(s2);
            if (l == 0) g_s0[0] = s2;
        }
    }
}

// ---------------------------------------------------------------------------
// Kernel 2: M[b,c,k] = sum_e G[c,e] Ctr[b,k,e] + u[c];  t[b,k] = v.Ctr[b,k]+s0
// grid 128 = (b*16 + kt), block 256 (c); 4 k per block.
// ---------------------------------------------------------------------------
__global__ void prep_M_kernel(const float* __restrict__ cf) {
    __shared__ __align__(16) float sC[4 * C_];
    int b  = blockIdx.x >> 4;
    int kt = blockIdx.x & 15;
    int tid = threadIdx.x;
    int w = tid >> 5, l = tid & 31;

    const float4* src = (const float4*)(cf + (size_t)(b * NC_ + kt * 4) * C_);
    ((float4*)sC)[tid] = src[tid];
    __syncthreads();

    int c = tid;
    float u = g_u[c];
    float acc[4] = {u, u, u, u};

    const float4* g4 = (const float4*)(g_G + (size_t)c * C_);
#pragma unroll 4
    for (int i = 0; i < C_ / 4; i++) {
        float4 g = g4[i];
#pragma unroll
        for (int j = 0; j < 4; j++) {
            acc[j] += g.x * sC[j * C_ + 4*i];
            acc[j] += g.y * sC[j * C_ + 4*i + 1];
            acc[j] += g.z * sC[j * C_ + 4*i + 2];
            acc[j] += g.w * sC[j * C_ + 4*i + 3];
        }
    }
#pragma unroll
    for (int j = 0; j < 4; j++)
        g_M[(size_t)(b * C_ + c) * NC_ + kt * 4 + j] = acc[j];

    if (w < 4) {   // t for this block's 4 centroids
        float s = 0.f;
#pragma unroll
        for (int j = 0; j < 8; j++) s += g_v[l + 32*j] * sC[w * C_ + l + 32*j];
        s = warp_sum(s);
        if (l == 0) g_t[b * NC_ + kt * 4 + w] = s + g_s0[0];
    }
}

// ---------------------------------------------------------------------------
// Kernel 3 (main): register-tiled. Block = 256 thr, 128 points.
// Thread tile: 4 pts (pt_g = tid>>3) x 8 k / 8 ch (k_g = tid&7, split octet
// {kg*4..+3} U {32+kg*4..+3} for conflict-free smem).
// smem: sM 16384 floats (M[b] then Ctr[b]); sPE 9728 floats (P chunk then E).
// ---------------------------------------------------------------------------
__global__ __launch_bounds__(256, 2)
void attn_main_kernel(const float* __restrict__ pf, const float* __restrict__ cf,
                      float* __restrict__ out) {
    extern __shared__ __align__(16) float sm[];
    float* sM  = sm;              // 16384 floats: M[c][64], later Ctr[k][256]
    float* sPE = sm + 16384;      // P chunk [pt][72] / E [pt][76]
    __shared__ __align__(16) float st[NC_];

    int b    = blockIdx.x >> 7;
    int tile = blockIdx.x & 127;
    int tid  = threadIdx.x;
    int pt_g = tid >> 3;          // 0..31 -> pts pt_g*4 .. +3
    int kg   = tid & 7;           // k/ch octet selector

    // ---- load M[b] (256x64) into sM, t into st ----
    const float4* Ms = (const float4*)(g_M + (size_t)b * C_ * NC_);
    float4* s4 = (float4*)sM;
#pragma unroll
    for (int i = 0; i < 16; i++) s4[tid + 256 * i] = Ms[tid + 256 * i];
    if (tid < NC_) st[tid] = g_t[b * NC_ + tid];

    size_t ptbase = (size_t)b * N_ + (size_t)tile * TP_;
    const float* pbase = pf + ptbase * C_;
    float* obase = out + ptbase * C_;

    // ---- phase 1: scores. acc[p][q]: q0,q1 -> k = kg*4+2q..; q2,q3 -> 32+kg*4+.. ----
    ull acc[4][4];
    __syncthreads();
    {
        const ull* t2 = (const ull*)st;
#pragma unroll
        for (int p = 0; p < 4; p++) {
            acc[p][0] = t2[2*kg];      acc[p][1] = t2[2*kg + 1];
            acc[p][2] = t2[16 + 2*kg]; acc[p][3] = t2[17 + 2*kg];
        }
    }

#pragma unroll 1
    for (int cc = 0; cc < 4; cc++) {
        if (cc) __syncthreads();
        // stage P[128 pts][64 ch chunk] into sPE[pt][72]
#pragma unroll
        for (int i = 0; i < 8; i++) {
            int q  = tid + 256 * i;
            int pt = q >> 4, jf = q & 15;
            float4 v = *(const float4*)(pbase + (size_t)pt * C_ + cc * 64 + jf * 4);
            *(float4*)(sPE + pt * SP_STRIDE + jf * 4) = v;
        }
        __syncthreads();

#pragma unroll 2
        for (int c4 = 0; c4 < 16; c4++) {
            float4 pv[4];
#pragma unroll
            for (int p = 0; p < 4; p++)
                pv[p] = *(const float4*)(sPE + (pt_g * 4 + p) * SP_STRIDE + c4 * 4);
#pragma unroll
            for (int j = 0; j < 4; j++) {
                const float* mrow = sM + (cc * 64 + c4 * 4 + j) * NC_;
                ulonglong2 m0 = *(const ulonglong2*)(mrow + kg * 4);
                ulonglong2 m1 = *(const ulonglong2*)(mrow + 32 + kg * 4);
                float pj[4] = {pv[0].x, pv[1].x, pv[2].x, pv[3].x};
                if (j == 1) { pj[0]=pv[0].y; pj[1]=pv[1].y; pj[2]=pv[2].y; pj[3]=pv[3].y; }
                else if (j == 2) { pj[0]=pv[0].z; pj[1]=pv[1].z; pj[2]=pv[2].z; pj[3]=pv[3].z; }
                else if (j == 3) { pj[0]=pv[0].w; pj[1]=pv[1].w; pj[2]=pv[2].w; pj[3]=pv[3].w; }
#pragma unroll
                for (int p = 0; p < 4; p++) {
                    ull pp = pack2(pj[p], pj[p]);
                    fma2(acc[p][0], m0.x, pp);
                    fma2(acc[p][1], m0.y, pp);
                    fma2(acc[p][2], m1.x, pp);
                    fma2(acc[p][3], m1.y, pp);
                }
            }
        }
    }
    __syncthreads();   // done with sM (M) and sPE (P)

    // ---- softmax per point (8 lanes of the kg-octet hold 8 k each) ----
#pragma unroll
    for (int p = 0; p < 4; p++) {
        float x0,x1,x2,x3,x4,x5,x6,x7;
        unpack2(acc[p][0], x0, x1); unpack2(acc[p][1], x2, x3);
        unpack2(acc[p][2], x4, x5); unpack2(acc[p][3], x6, x7);
        float mx = fmaxf(fmaxf(fmaxf(x0,x1),fmaxf(x2,x3)), fmaxf(fmaxf(x4,x5),fmaxf(x6,x7)));
#pragma unroll
        for (int off = 1; off < 8; off <<= 1)
            mx = fmaxf(mx, __shfl_xor_sync(0xffffffffu, mx, off));
        x0 = __expf(x0-mx); x1 = __expf(x1-mx); x2 = __expf(x2-mx); x3 = __expf(x3-mx);
        x4 = __expf(x4-mx); x5 = __expf(x5-mx); x6 = __expf(x6-mx); x7 = __expf(x7-mx);
        float s = ((x0+x1)+(x2+x3)) + ((x4+x5)+(x6+x7));
#pragma unroll
        for (int off = 1; off < 8; off <<= 1)
            s += __shfl_xor_sync(0xffffffffu, s, off);
        float inv = 1.0f / s;
        acc[p][0] = pack2(x0*inv, x1*inv); acc[p][1] = pack2(x2*inv, x3*inv);
        acc[p][2] = pack2(x4*inv, x5*inv); acc[p][3] = pack2(x6*inv, x7*inv);
    }

    // ---- write E to sPE[pt][76]; copy Ctr[b] into sM ----
#pragma unroll
    for (int p = 0; p < 4; p++) {
        float* er = sPE + (pt_g * 4 + p) * SE_STRIDE;
        ulonglong2 e0; e0.x = acc[p][0]; e0.y = acc[p][1];
        ulonglong2 e1; e1.x = acc[p][2]; e1.y = acc[p][3];
        *(ulonglong2*)(er + kg * 4)      = e0;
        *(ulonglong2*)(er + 32 + kg * 4) = e1;
    }
    {
        const float4* Cs = (const float4*)(cf + (size_t)b * NC_ * C_);
#pragma unroll
        for (int i = 0; i < 16; i++) s4[tid + 256 * i] = Cs[tid + 256 * i];
    }
    __syncthreads();

    // ---- phase 2: out[pt][ch] = P + sum_k E[pt][k] * Ctr[k][ch] ----
#pragma unroll 1
    for (int cc = 0; cc < 4; cc++) {
        ull a2[4][4];
#pragma unroll
        for (int p = 0; p < 4; p++)
#pragma unroll
            for (int r = 0; r < 4; r++) a2[p][r] = 0ull;

#pragma unroll 2
        for (int k4 = 0; k4 < 16; k4++) {
            float4 ev[4];
#pragma unroll
            for (int p = 0; p < 4; p++)
                ev[p] = *(const float4*)(sPE + (pt_g * 4 + p) * SE_STRIDE + k4 * 4);
#pragma unroll
            for (int j = 0; j < 4; j++) {
                const float* crow = sM + (k4 * 4 + j) * C_ + cc * 64;
                ulonglong2 c0 = *(const ulonglong2*)(crow + kg * 4);
                ulonglong2 c1 = *(const ulonglong2*)(crow + 32 + kg * 4);
                float ej[4] = {ev[0].x, ev[1].x, ev[2].x, ev[3].x};
                if (j == 1) { ej[0]=ev[0].y; ej[1]=ev[1].y; ej[2]=ev[2].y; ej[3]=ev[3].y; }
                else if (j == 2) { ej[0]=ev[0].z; ej[1]=ev[1].z; ej[2]=ev[2].z; ej[3]=ev[3].z; }
                else if (j == 3) { ej[0]=ev[0].w; ej[1]=ev[1].w; ej[2]=ev[2].w; ej[3]=ev[3].w; }
#pragma unroll
                for (int p = 0; p < 4; p++) {
                    ull pp = pack2(ej[p], ej[p]);
                    fma2(a2[p][0], c0.x, pp);
                    fma2(a2[p][1], c0.y, pp);
                    fma2(a2[p][2], c1.x, pp);
                    fma2(a2[p][3], c1.y, pp);
                }
            }
        }
        // epilogue: residual + store (perfectly coalesced: 8 kg x 16B contiguous)
#pragma unroll
        for (int p = 0; p < 4; p++) {
            size_t roff = (size_t)(pt_g * 4 + p) * C_ + cc * 64 + kg * 4;
            float4 v0 = *(const float4*)(pbase + roff);
            float4 v1 = *(const float4*)(pbase + roff + 32);
            float a,bv;
            unpack2(a2[p][0], a, bv); v0.x += a; v0.y += bv;
            unpack2(a2[p][1], a, bv); v0.z += a; v0.w += bv;
            unpack2(a2[p][2], a, bv); v1.x += a; v1.y += bv;
            unpack2(a2[p][3], a, bv); v1.z += a; v1.w += bv;
            *(float4*)(obase + roff)      = v0;
            *(float4*)(obase + roff + 32) = v1;
        }
    }
}

// ---------------------------------------------------------------------------
extern "C" void kernel_launch(void* const* d_in, const int* in_sizes, int n_in,
                              void* d_out, int out_size) {
    const float* pf = (const float*)d_in[0];   // point_features   (B,N,C)
    const float* cf = (const float*)d_in[1];   // centroid_features(B,NC,C)
    const float* Wp = (const float*)d_in[2];   // (C,C)
    const float* bp = (const float*)d_in[3];   // (C,)
    const float* Wc = (const float*)d_in[4];   // (C,C)
    const float* bc = (const float*)d_in[5];   // (C,)
    float* out = (float*)d_out;

    const int smem_bytes = (16384 + TP_ * SE_STRIDE) * sizeof(float);

    static bool attr_set = false;
    if (!attr_set) {
        cudaFuncSetAttribute(attn_main_kernel,
                             cudaFuncAttributeMaxDynamicSharedMemorySize,
                             smem_bytes);
        attr_set = true;
    }

    prep_G_kernel<<<C_, C_>>>(Wp, Wc, bp, bc);
    prep_M_kernel<<<B_ * 16, 256>>>(cf);
    attn_main_kernel<<<B_ * (N_ / TP_), 256, smem_bytes>>>(pf, cf, out);
}